// round 11
// baseline (speedup 1.0000x reference)
#include <cuda_runtime.h>
#include <cuda_fp16.h>
#include <math.h>
#include <stdint.h>

// RoutingLayer via mma.sync m16n8k16 fp16 (portable PTX for sm_103 target).
// out[B,64] = scatter(softmax(top2(x@w_gate + noise*(softplus(x@w_noise)+0.01))))
// B=32768, D=2048, E=64. Fused GEMM N=128 (0..63 gate, 64..127 noise).
// FP16x2 split: x=h0+h1, (256*w)=h0+h1; h0h0 + h0h1 + h1h0, scaled 2^-8.
// R11 = R10 + BKC=64 (32 chunks, half the barriers) + section-granular A
// pipeline: per k16-section issue LDG(sec+2) / cvt(sec+1) / MMA(sec) with
// ping-pong raw + fragment registers. B in 3-stage cp.async ring (96KB).

#define KDIM 2048
#define EDIM 64
#define BM   128
#define BKC  64
#define NCHUNK (KDIM / BKC)   // 32
#define NSEC  128             // k16 sections total
#define TPB  128
#define NBUF 3

// smem: B ring. Per buffer 2048 16B-units: unit = s*512 + n*4 + tig (s=0..3)
#define BUF_U 2048
#define SMEM_BYTES (NBUF * BUF_U * 16)   // 98304

// pre-split weights: [k16 step s(128)][n(128)][tig(4)] uint4 = (b0_h0,b1_h0,b0_h1,b1_h1)
__device__ uint4 g_wb[128 * 128 * 4];   // 1 MB

__device__ __forceinline__ uint32_t pack2(__half lo, __half hi) {
    __half2 h = __halves2half2(lo, hi);
    return *(uint32_t*)&h;
}

__device__ __forceinline__ void mma16(float* c, uint32_t a0, uint32_t a1,
                                      uint32_t a2, uint32_t a3,
                                      uint32_t b0, uint32_t b1) {
    asm volatile(
        "mma.sync.aligned.m16n8k16.row.col.f32.f16.f16.f32 "
        "{%0,%1,%2,%3}, {%4,%5,%6,%7}, {%8,%9}, {%0,%1,%2,%3};"
        : "+f"(c[0]), "+f"(c[1]), "+f"(c[2]), "+f"(c[3])
        : "r"(a0), "r"(a1), "r"(a2), "r"(a3), "r"(b0), "r"(b1));
}

__device__ __forceinline__ uint32_t smem_u32(const void* p) {
    uint32_t a;
    asm("{ .reg .u64 t; cvta.to.shared.u64 t, %1; cvt.u32.u64 %0, t; }" : "=r"(a) : "l"(p));
    return a;
}
#define CP_ASYNC16(dst, src) \
    asm volatile("cp.async.cg.shared.global [%0], [%1], 16;" :: "r"(dst), "l"(src) : "memory")
#define CP_COMMIT() asm volatile("cp.async.commit_group;" ::: "memory")
#define CP_WAIT1()  asm volatile("cp.async.wait_group 1;" ::: "memory")

// ---- prep: split 256*w into fp16 (h0,h1), fragment-native B layout ----
__global__ void prep_w(const float* __restrict__ wg, const float* __restrict__ wn) {
    const int idx = blockIdx.x * blockDim.x + threadIdx.x;  // 0..65535
    const int tig = idx & 3;
    const int n   = (idx >> 2) & 127;
    const int s   = idx >> 9;            // k16 step 0..127
    const int kb  = s * 16;
    const int kk[4] = {kb + 2*tig, kb + 2*tig + 1, kb + 2*tig + 8, kb + 2*tig + 9};
    float v[4];
    #pragma unroll
    for (int j = 0; j < 4; j++)
        v[j] = 256.0f * ((n < 64) ? wg[kk[j] * 64 + n] : wn[kk[j] * 64 + (n - 64)]);
    __half h0[4], h1[4];
    #pragma unroll
    for (int j = 0; j < 4; j++) {
        h0[j] = __float2half_rn(v[j]);
        h1[j] = __float2half_rn(v[j] - __half2float(h0[j]));
    }
    uint4 w4;
    w4.x = pack2(h0[0], h0[1]);
    w4.y = pack2(h0[2], h0[3]);
    w4.z = pack2(h1[0], h1[1]);
    w4.w = pack2(h1[2], h1[3]);
    g_wb[(size_t)(s * 128 + n) * 4 + tig] = w4;
}

// convert 4 raw float2 k-pairs into one mma A fragment (hi + lo)
__device__ __forceinline__ void cvt4(const float2 r0, const float2 r1,
                                     const float2 r2, const float2 r3,
                                     uint32_t* ah, uint32_t* al) {
    const float2 rr[4] = {r0, r1, r2, r3};
    #pragma unroll
    for (int j = 0; j < 4; j++) {
        __half a = __float2half_rn(rr[j].x);
        __half b = __float2half_rn(rr[j].y);
        ah[j] = pack2(a, b);
        al[j] = pack2(__float2half_rn(rr[j].x - __half2float(a)),
                      __float2half_rn(rr[j].y - __half2float(b)));
    }
}

// load one k16-section's raw A pairs for this lane (8 float2)
__device__ __forceinline__ void load_raw8(const float* const* xr, int k0, float2* r8) {
    #pragma unroll
    for (int rr = 0; rr < 4; rr++) {
        r8[rr]     = *(const float2*)(xr[rr] + k0);
        r8[rr + 4] = *(const float2*)(xr[rr] + k0 + 8);
    }
}

// cvt one section: raw8 -> fragments (mt0: ah[0..3], mt1: ah[4..7])
__device__ __forceinline__ void cvt8(const float2* r8, uint32_t* ah, uint32_t* al) {
    cvt4(r8[0], r8[1], r8[4], r8[5], &ah[0], &al[0]);
    cvt4(r8[2], r8[3], r8[6], r8[7], &ah[4], &al[4]);
}

__device__ __forceinline__ void issue_b(uint32_t sb, int buf, int chunk) {
    const uint4* src = g_wb + (size_t)chunk * BUF_U + threadIdx.x;
    #pragma unroll
    for (int j = 0; j < 16; j++) {
        uint32_t dst = sb + (uint32_t)(buf * BUF_U + j * 128 + threadIdx.x) * 16u;
        CP_ASYNC16(dst, src + j * 128);
    }
    CP_COMMIT();
}

// ---- main ----
__global__ __launch_bounds__(TPB, 2)
void routing_mma(const float* __restrict__ x,
                 const float* __restrict__ nz,
                 float* __restrict__ out)
{
    extern __shared__ uint4 sm4[];
    const int tid = threadIdx.x;
    const int wid = tid >> 5;            // 0..3
    const int lane = tid & 31;
    const int gid = lane >> 2;
    const int tig = lane & 3;
    const int r0 = blockIdx.x * BM;
    const int m0 = wid * 32;             // warp rows [m0, m0+32)

    float c[2][16][4];
    #pragma unroll
    for (int mt = 0; mt < 2; mt++)
        #pragma unroll
        for (int nt = 0; nt < 16; nt++)
            #pragma unroll
            for (int j = 0; j < 4; j++) c[mt][nt][j] = 0.f;

    // A direct-gmem pointers for this lane's fragment rows
    const float* xr[4];
    #pragma unroll
    for (int rr = 0; rr < 4; rr++)
        xr[rr] = x + (size_t)(r0 + m0 + gid + 8 * rr) * KDIM + 2 * tig;

    const uint32_t sb = smem_u32(sm4);

    // ping-pong A state: F[p] = fragments of section with parity p,
    // raw[p] = raw data of a section with parity p
    uint32_t ah[2][8], al[2][8];
    float2 raw[2][8];

    // ---- prologue ----
    load_raw8(xr, 0, raw[0]);           // sec 0
    load_raw8(xr, 16, raw[1]);          // sec 1
    issue_b(sb, 0, 0);
    issue_b(sb, 1, 1);
    cvt8(raw[0], ah[0], al[0]);         // F[0] = frags(sec 0)

    for (int t = 0; t < NCHUNK; t++) {
        CP_WAIT1();              // chunk t resident (chunk t+1 may still fly)
        __syncthreads();         // all warps done with buf[(t-1)%3]
        if (t + 2 < NCHUNK) issue_b(sb, (t + 2) % NBUF, t + 2);

        const uint4* buf = sm4 + (t % NBUF) * BUF_U;
        const bool notlast = (t + 1 < NCHUNK);

        #pragma unroll
        for (int s = 0; s < 4; s++) {
            const int par = s & 1;
            const int parn = (s + 1) & 1;
            // LDG raw(sec+2) into raw[par] (freed by cvt one section ago)
            if (notlast || s < 2)
                load_raw8(xr, (t * 4 + s + 2) * 16, raw[par]);
            // cvt raw(sec+1) -> F[parn]
            if (notlast || s < 3)
                cvt8(raw[parn], ah[parn], al[parn]);
            // MMAs for section sec from F[par]; B from smem
            const uint4* bb = buf + s * 512;
            const uint32_t* h = ah[par];
            const uint32_t* l = al[par];
            #pragma unroll
            for (int nt = 0; nt < 16; nt += 2) {
                uint4 B0 = bb[((nt)     * 8 + gid) * 4 + tig];
                uint4 B1 = bb[((nt + 1) * 8 + gid) * 4 + tig];
                // dep distance 4; per-acc term order h0h0, h0h1, h1h0
                mma16(c[0][nt],   h[0], h[1], h[2], h[3], B0.x, B0.y);
                mma16(c[1][nt],   h[4], h[5], h[6], h[7], B0.x, B0.y);
                mma16(c[0][nt+1], h[0], h[1], h[2], h[3], B1.x, B1.y);
                mma16(c[1][nt+1], h[4], h[5], h[6], h[7], B1.x, B1.y);
                mma16(c[0][nt],   h[0], h[1], h[2], h[3], B0.z, B0.w);
                mma16(c[1][nt],   h[4], h[5], h[6], h[7], B0.z, B0.w);
                mma16(c[0][nt+1], h[0], h[1], h[2], h[3], B1.z, B1.w);
                mma16(c[1][nt+1], h[4], h[5], h[6], h[7], B1.z, B1.w);
                mma16(c[0][nt],   l[0], l[1], l[2], l[3], B0.x, B0.y);
                mma16(c[1][nt],   l[4], l[5], l[6], l[7], B0.x, B0.y);
                mma16(c[0][nt+1], l[0], l[1], l[2], l[3], B1.x, B1.y);
                mma16(c[1][nt+1], l[4], l[5], l[6], l[7], B1.x, B1.y);
            }
        }
    }

    // ---- epilogue: 4 rows per lane (gid+8*hh), intra-quad top-2 ----
    const float S = 1.0f / 256.0f;   // undo weight pre-scale (exact)
    float v1[4] = {-INFINITY, -INFINITY, -INFINITY, -INFINITY};
    float v2[4] = {-INFINITY, -INFINITY, -INFINITY, -INFINITY};
    int   i1[4] = {0x7fffffff, 0x7fffffff, 0x7fffffff, 0x7fffffff};
    int   i2[4] = {0x7fffffff, 0x7fffffff, 0x7fffffff, 0x7fffffff};

    #pragma unroll
    for (int hh = 0; hh < 4; hh++) {
        const int row = r0 + m0 + gid + 8 * hh;
        const int mt = hh >> 1;
        const int jb = (hh & 1) * 2;
        #pragma unroll
        for (int nt = 0; nt < 8; nt++) {
            const int e0 = nt * 8 + 2 * tig;
            float2 z = *(const float2*)(nz + (size_t)row * EDIM + e0);
            const float zf[2] = {z.x, z.y};
            #pragma unroll
            for (int j = 0; j < 2; j++) {
                float g = c[mt][nt][jb + j] * S;
                float s = c[mt][nt + 8][jb + j] * S;
                float sp = fmaxf(s, 0.f) + log1pf(expf(-fabsf(s)));
                float v = fmaf(zf[j], sp + 0.01f, g);
                const int e = e0 + j;
                if (v > v1[hh])      { v2[hh] = v1[hh]; i2[hh] = i1[hh]; v1[hh] = v; i1[hh] = e; }
                else if (v > v2[hh]) { v2[hh] = v; i2[hh] = e; }
            }
        }
    }

    #pragma unroll
    for (int hh = 0; hh < 4; hh++) {
        #pragma unroll
        for (int off = 1; off < 4; off <<= 1) {
            float ov1 = __shfl_xor_sync(0xffffffffu, v1[hh], off);
            int   oi1 = __shfl_xor_sync(0xffffffffu, i1[hh], off);
            float ov2 = __shfl_xor_sync(0xffffffffu, v2[hh], off);
            int   oi2 = __shfl_xor_sync(0xffffffffu, i2[hh], off);
            bool firstMine = (v1[hh] > ov1) || (v1[hh] == ov1 && i1[hh] < oi1);
            float nv1, nv2; int ni1, ni2;
            if (firstMine) {
                nv1 = v1[hh]; ni1 = i1[hh];
                bool s2 = (v2[hh] > ov1) || (v2[hh] == ov1 && i2[hh] < oi1);
                nv2 = s2 ? v2[hh] : ov1; ni2 = s2 ? i2[hh] : oi1;
            } else {
                nv1 = ov1; ni1 = oi1;
                bool s2 = (ov2 > v1[hh]) || (ov2 == v1[hh] && oi2 < i1[hh]);
                nv2 = s2 ? ov2 : v1[hh]; ni2 = s2 ? oi2 : i1[hh];
            }
            v1[hh] = nv1; i1[hh] = ni1; v2[hh] = nv2; i2[hh] = ni2;
        }
    }

    #pragma unroll
    for (int hh = 0; hh < 4; hh++) {
        float e2 = expf(v2[hh] - v1[hh]);
        float denom = 1.f + e2;
        float g1 = 1.f / denom;
        float g2 = e2 / denom;
        const int row = r0 + m0 + gid + 8 * hh;
        #pragma unroll
        for (int nt = 0; nt < 8; nt++) {
            const int e0 = nt * 8 + 2 * tig;
            float2 o;
            o.x = (e0 == i1[hh]) ? g1 : ((e0 == i2[hh]) ? g2 : 0.f);
            o.y = (e0 + 1 == i1[hh]) ? g1 : ((e0 + 1 == i2[hh]) ? g2 : 0.f);
            *(float2*)(out + (size_t)row * EDIM + e0) = o;
        }
    }
}

extern "C" void kernel_launch(void* const* d_in, const int* in_sizes, int n_in,
                              void* d_out, int out_size)
{
    const float* x  = (const float*)d_in[0];   // [32768, 2048]
    const float* wg = (const float*)d_in[1];   // [2048, 64]
    const float* wn = (const float*)d_in[2];   // [2048, 64]
    const float* nz = (const float*)d_in[3];   // [32768, 64]
    float* out = (float*)d_out;                // [32768, 64]

    prep_w<<<256, 256>>>(wg, wn);

    cudaFuncSetAttribute(routing_mma, cudaFuncAttributeMaxDynamicSharedMemorySize,
                         SMEM_BYTES);
    const int B = in_sizes[0] / KDIM;          // 32768
    routing_mma<<<B / BM, TPB, SMEM_BYTES>>>(x, nz, out);
}

// round 12
// speedup vs baseline: 1.1092x; 1.1092x over previous
#include <cuda_runtime.h>
#include <cuda_fp16.h>
#include <math.h>
#include <stdint.h>

// RoutingLayer via mma.sync m16n8k16 fp16 (portable PTX for sm_103 target).
// out[B,64] = scatter(softmax(top2(x@w_gate + noise*(softplus(x@w_noise)+0.01))))
// B=32768, D=2048, E=64. Fused GEMM N=128 (0..63 gate, 64..127 noise).
// FP16x2 split: x=h0+h1, (256*w)=h0+h1; h0h0 + h0h1 + h1h0, scaled 2^-8.
// R12 = R10 (best, 142us) + explicit B-LDS ping-pong (load next nt-pair while
// issuing current 12 MMAs), A-LDGs hoisted above the cp.async wait, and a
// register diet (base pointer + immediate offsets instead of xr[4]).

#define KDIM 2048
#define EDIM 64
#define BM   128
#define BKC  32
#define NCHUNK (KDIM / BKC)   // 64
#define TPB  128
#define NBUF 3

// smem: B ring. Per buffer 1024 16B-units: unit = s*512 + n*4 + tig
#define BUF_U 1024
#define SMEM_BYTES (NBUF * BUF_U * 16)   // 49152

// pre-split weights: [k16 step s(128)][n(128)][tig(4)] uint4 = (b0_h0,b1_h0,b0_h1,b1_h1)
__device__ uint4 g_wb[128 * 128 * 4];   // 1 MB

__device__ __forceinline__ uint32_t pack2(__half lo, __half hi) {
    __half2 h = __halves2half2(lo, hi);
    return *(uint32_t*)&h;
}

__device__ __forceinline__ void mma16(float* c, uint32_t a0, uint32_t a1,
                                      uint32_t a2, uint32_t a3,
                                      uint32_t b0, uint32_t b1) {
    asm volatile(
        "mma.sync.aligned.m16n8k16.row.col.f32.f16.f16.f32 "
        "{%0,%1,%2,%3}, {%4,%5,%6,%7}, {%8,%9}, {%0,%1,%2,%3};"
        : "+f"(c[0]), "+f"(c[1]), "+f"(c[2]), "+f"(c[3])
        : "r"(a0), "r"(a1), "r"(a2), "r"(a3), "r"(b0), "r"(b1));
}

__device__ __forceinline__ uint32_t smem_u32(const void* p) {
    uint32_t a;
    asm("{ .reg .u64 t; cvta.to.shared.u64 t, %1; cvt.u32.u64 %0, t; }" : "=r"(a) : "l"(p));
    return a;
}
#define CP_ASYNC16(dst, src) \
    asm volatile("cp.async.cg.shared.global [%0], [%1], 16;" :: "r"(dst), "l"(src) : "memory")
#define CP_COMMIT() asm volatile("cp.async.commit_group;" ::: "memory")
#define CP_WAIT1()  asm volatile("cp.async.wait_group 1;" ::: "memory")

// ---- prep: split 256*w into fp16 (h0,h1), fragment-native B layout ----
__global__ void prep_w(const float* __restrict__ wg, const float* __restrict__ wn) {
    const int idx = blockIdx.x * blockDim.x + threadIdx.x;  // 0..65535
    const int tig = idx & 3;
    const int n   = (idx >> 2) & 127;
    const int s   = idx >> 9;            // k16 step 0..127
    const int kb  = s * 16;
    const int kk[4] = {kb + 2*tig, kb + 2*tig + 1, kb + 2*tig + 8, kb + 2*tig + 9};
    float v[4];
    #pragma unroll
    for (int j = 0; j < 4; j++)
        v[j] = 256.0f * ((n < 64) ? wg[kk[j] * 64 + n] : wn[kk[j] * 64 + (n - 64)]);
    __half h0[4], h1[4];
    #pragma unroll
    for (int j = 0; j < 4; j++) {
        h0[j] = __float2half_rn(v[j]);
        h1[j] = __float2half_rn(v[j] - __half2float(h0[j]));
    }
    uint4 w4;
    w4.x = pack2(h0[0], h0[1]);
    w4.y = pack2(h0[2], h0[3]);
    w4.z = pack2(h1[0], h1[1]);
    w4.w = pack2(h1[2], h1[3]);
    g_wb[(size_t)(s * 128 + n) * 4 + tig] = w4;
}

// convert 4 raw float2 k-pairs into one mma A fragment (hi + lo)
__device__ __forceinline__ void cvt4(const float2 r0, const float2 r1,
                                     const float2 r2, const float2 r3,
                                     uint32_t* ah, uint32_t* al) {
    const float2 rr[4] = {r0, r1, r2, r3};
    #pragma unroll
    for (int j = 0; j < 4; j++) {
        __half a = __float2half_rn(rr[j].x);
        __half b = __float2half_rn(rr[j].y);
        ah[j] = pack2(a, b);
        al[j] = pack2(__float2half_rn(rr[j].x - __half2float(a)),
                      __float2half_rn(rr[j].y - __half2float(b)));
    }
}

// load next chunk's raw A pairs from one base pointer (immediate row offsets)
__device__ __forceinline__ void load_raw(const float* xbase, int k0, float2* raw) {
    #pragma unroll
    for (int s = 0; s < 2; s++)
        #pragma unroll
        for (int rr = 0; rr < 4; rr++) {
            raw[s * 8 + rr]     = *(const float2*)(xbase + rr * 8 * KDIM + k0 + s * 16);
            raw[s * 8 + rr + 4] = *(const float2*)(xbase + rr * 8 * KDIM + k0 + s * 16 + 8);
        }
}

__device__ __forceinline__ void cvt_all(const float2* raw, uint32_t (*ah)[8],
                                        uint32_t (*al)[8]) {
    #pragma unroll
    for (int s = 0; s < 2; s++) {
        cvt4(raw[s*8+0], raw[s*8+1], raw[s*8+4], raw[s*8+5], &ah[s][0], &al[s][0]);
        cvt4(raw[s*8+2], raw[s*8+3], raw[s*8+6], raw[s*8+7], &ah[s][4], &al[s][4]);
    }
}

__device__ __forceinline__ void issue_b(uint32_t sb, int buf, int chunk) {
    const uint4* src = g_wb + (size_t)chunk * 1024 + threadIdx.x;
    #pragma unroll
    for (int j = 0; j < 8; j++) {
        uint32_t dst = sb + (uint32_t)(buf * BUF_U + j * 128 + threadIdx.x) * 16u;
        CP_ASYNC16(dst, src + j * 128);
    }
    CP_COMMIT();
}

// ---- main ----
__global__ __launch_bounds__(TPB, 2)
void routing_mma(const float* __restrict__ x,
                 const float* __restrict__ nz,
                 float* __restrict__ out)
{
    extern __shared__ uint4 sm4[];
    const int tid = threadIdx.x;
    const int wid = tid >> 5;            // 0..3
    const int lane = tid & 31;
    const int gid = lane >> 2;
    const int tig = lane & 3;
    const int r0 = blockIdx.x * BM;
    const int m0 = wid * 32;             // warp rows [m0, m0+32)

    float c[2][16][4];
    #pragma unroll
    for (int mt = 0; mt < 2; mt++)
        #pragma unroll
        for (int nt = 0; nt < 16; nt++)
            #pragma unroll
            for (int j = 0; j < 4; j++) c[mt][nt][j] = 0.f;

    // single A base pointer; rows at immediate offsets rr*8*KDIM
    const float* xbase = x + (size_t)(r0 + m0 + gid) * KDIM + 2 * tig;

    const uint32_t sb = smem_u32(sm4);

    uint32_t ah[2][8], al[2][8];   // current chunk fragments (s half; mt0:0-3, mt1:4-7)
    float2 raw[16];                // prefetched next-chunk raw pairs

    // ---- prologue: B chunks 0,1 in flight; A chunk 0 converted ----
    load_raw(xbase, 0, raw);
    issue_b(sb, 0, 0);
    issue_b(sb, 1, 1);
    cvt_all(raw, ah, al);

    for (int t = 0; t < NCHUNK; t++) {
        // A-LDGs for t+1 issued BEFORE the wait: near-full-chunk shadow
        if (t + 1 < NCHUNK) load_raw(xbase, (t + 1) * BKC, raw);
        CP_WAIT1();              // chunk t resident (chunk t+1 may still fly)
        __syncthreads();         // all warps done with buf[(t-1)%3]
        if (t + 2 < NCHUNK) issue_b(sb, (t + 2) % NBUF, t + 2);

        // ---- compute chunk t: B ping-pong in regs, A from registers ----
        {
            const uint4* bb0 = sm4 + (t % NBUF) * BUF_U;
            const uint4* bb1 = bb0 + 512;
            uint4 B0 = bb0[(0 * 8 + gid) * 4 + tig];
            uint4 B1 = bb0[(1 * 8 + gid) * 4 + tig];
            #pragma unroll
            for (int s = 0; s < 2; s++) {
                const uint4* bb = s ? bb1 : bb0;
                const uint32_t* h = ah[s];
                const uint32_t* l = al[s];
                #pragma unroll
                for (int ntp = 0; ntp < 8; ntp++) {
                    const int nt = ntp * 2;
                    uint4 C0 = B0, C1 = B1;
                    // prefetch next nt-pair while the 12 MMAs below issue
                    if (!(s == 1 && ntp == 7)) {
                        const uint4* nb = (ntp == 7) ? bb1 : bb;
                        const int nnt = (ntp == 7) ? 0 : nt + 2;
                        B0 = nb[((nnt)     * 8 + gid) * 4 + tig];
                        B1 = nb[((nnt + 1) * 8 + gid) * 4 + tig];
                    }
                    // dep distance 4; per-acc term order h0h0, h0h1, h1h0
                    mma16(c[0][nt],   h[0], h[1], h[2], h[3], C0.x, C0.y);
                    mma16(c[1][nt],   h[4], h[5], h[6], h[7], C0.x, C0.y);
                    mma16(c[0][nt+1], h[0], h[1], h[2], h[3], C1.x, C1.y);
                    mma16(c[1][nt+1], h[4], h[5], h[6], h[7], C1.x, C1.y);
                    mma16(c[0][nt],   h[0], h[1], h[2], h[3], C0.z, C0.w);
                    mma16(c[1][nt],   h[4], h[5], h[6], h[7], C0.z, C0.w);
                    mma16(c[0][nt+1], h[0], h[1], h[2], h[3], C1.z, C1.w);
                    mma16(c[1][nt+1], h[4], h[5], h[6], h[7], C1.z, C1.w);
                    mma16(c[0][nt],   l[0], l[1], l[2], l[3], C0.x, C0.y);
                    mma16(c[1][nt],   l[4], l[5], l[6], l[7], C0.x, C0.y);
                    mma16(c[0][nt+1], l[0], l[1], l[2], l[3], C1.x, C1.y);
                    mma16(c[1][nt+1], l[4], l[5], l[6], l[7], C1.x, C1.y);
                }
            }
        }

        if (t + 1 < NCHUNK) cvt_all(raw, ah, al);   // fragments for t+1
    }

    // ---- epilogue: 4 rows per lane (gid+8*hh), intra-quad top-2 ----
    const float S = 1.0f / 256.0f;   // undo weight pre-scale (exact)
    float v1[4] = {-INFINITY, -INFINITY, -INFINITY, -INFINITY};
    float v2[4] = {-INFINITY, -INFINITY, -INFINITY, -INFINITY};
    int   i1[4] = {0x7fffffff, 0x7fffffff, 0x7fffffff, 0x7fffffff};
    int   i2[4] = {0x7fffffff, 0x7fffffff, 0x7fffffff, 0x7fffffff};

    #pragma unroll
    for (int hh = 0; hh < 4; hh++) {
        const int row = r0 + m0 + gid + 8 * hh;
        const int mt = hh >> 1;
        const int jb = (hh & 1) * 2;
        #pragma unroll
        for (int nt = 0; nt < 8; nt++) {
            const int e0 = nt * 8 + 2 * tig;
            float2 z = *(const float2*)(nz + (size_t)row * EDIM + e0);
            const float zf[2] = {z.x, z.y};
            #pragma unroll
            for (int j = 0; j < 2; j++) {
                float g = c[mt][nt][jb + j] * S;
                float s = c[mt][nt + 8][jb + j] * S;
                float sp = fmaxf(s, 0.f) + log1pf(expf(-fabsf(s)));
                float v = fmaf(zf[j], sp + 0.01f, g);
                const int e = e0 + j;
                if (v > v1[hh])      { v2[hh] = v1[hh]; i2[hh] = i1[hh]; v1[hh] = v; i1[hh] = e; }
                else if (v > v2[hh]) { v2[hh] = v; i2[hh] = e; }
            }
        }
    }

    #pragma unroll
    for (int hh = 0; hh < 4; hh++) {
        #pragma unroll
        for (int off = 1; off < 4; off <<= 1) {
            float ov1 = __shfl_xor_sync(0xffffffffu, v1[hh], off);
            int   oi1 = __shfl_xor_sync(0xffffffffu, i1[hh], off);
            float ov2 = __shfl_xor_sync(0xffffffffu, v2[hh], off);
            int   oi2 = __shfl_xor_sync(0xffffffffu, i2[hh], off);
            bool firstMine = (v1[hh] > ov1) || (v1[hh] == ov1 && i1[hh] < oi1);
            float nv1, nv2; int ni1, ni2;
            if (firstMine) {
                nv1 = v1[hh]; ni1 = i1[hh];
                bool s2 = (v2[hh] > ov1) || (v2[hh] == ov1 && i2[hh] < oi1);
                nv2 = s2 ? v2[hh] : ov1; ni2 = s2 ? i2[hh] : oi1;
            } else {
                nv1 = ov1; ni1 = oi1;
                bool s2 = (ov2 > v1[hh]) || (ov2 == v1[hh] && oi2 < i1[hh]);
                nv2 = s2 ? ov2 : v1[hh]; ni2 = s2 ? oi2 : i1[hh];
            }
            v1[hh] = nv1; i1[hh] = ni1; v2[hh] = nv2; i2[hh] = ni2;
        }
    }

    #pragma unroll
    for (int hh = 0; hh < 4; hh++) {
        float e2 = expf(v2[hh] - v1[hh]);
        float denom = 1.f + e2;
        float g1 = 1.f / denom;
        float g2 = e2 / denom;
        const int row = r0 + m0 + gid + 8 * hh;
        #pragma unroll
        for (int nt = 0; nt < 8; nt++) {
            const int e0 = nt * 8 + 2 * tig;
            float2 o;
            o.x = (e0 == i1[hh]) ? g1 : ((e0 == i2[hh]) ? g2 : 0.f);
            o.y = (e0 + 1 == i1[hh]) ? g1 : ((e0 + 1 == i2[hh]) ? g2 : 0.f);
            *(float2*)(out + (size_t)row * EDIM + e0) = o;
        }
    }
}

extern "C" void kernel_launch(void* const* d_in, const int* in_sizes, int n_in,
                              void* d_out, int out_size)
{
    const float* x  = (const float*)d_in[0];   // [32768, 2048]
    const float* wg = (const float*)d_in[1];   // [2048, 64]
    const float* wn = (const float*)d_in[2];   // [2048, 64]
    const float* nz = (const float*)d_in[3];   // [32768, 64]
    float* out = (float*)d_out;                // [32768, 64]

    prep_w<<<256, 256>>>(wg, wn);

    cudaFuncSetAttribute(routing_mma, cudaFuncAttributeMaxDynamicSharedMemorySize,
                         SMEM_BYTES);
    const int B = in_sizes[0] / KDIM;          // 32768
    routing_mma<<<B / BM, TPB, SMEM_BYTES>>>(x, nz, out);
}